// round 10
// baseline (speedup 1.0000x reference)
#include <cuda_runtime.h>
#include <cuda_bf16.h>
#include <cstdint>

typedef unsigned long long u64;

#define B_DIM 4096
#define T_DIM 1024
#define VOCAB 32000
#define HID 16

// ---------------- scratch (no allocations allowed) ----------------
__device__ float g_P[VOCAB * HID];   // projected embedding table: Wx@e + b (2 MB)
__device__ float g_H[B_DIM * HID];   // final hidden states (256 KB)

// ---------------- f32x2 helpers ----------------
__device__ __forceinline__ u64 pack2(float x, float y) {
    u64 r; asm("mov.b64 %0, {%1, %2};" : "=l"(r) : "f"(x), "f"(y)); return r;
}
__device__ __forceinline__ float2 unpack2(u64 v) {
    float2 f; asm("mov.b64 {%0, %1}, %2;" : "=f"(f.x), "=f"(f.y) : "l"(v)); return f;
}
__device__ __forceinline__ u64 ffma2(u64 a, u64 b, u64 c) {
    u64 d; asm("fma.rn.f32x2 %0, %1, %2, %3;" : "=l"(d) : "l"(a), "l"(b), "l"(c)); return d;
}
__device__ __forceinline__ u64 add2(u64 a, u64 b) {
    u64 d; asm("add.rn.f32x2 %0, %1, %2;" : "=l"(d) : "l"(a), "l"(b)); return d;
}

// ---------------- kernel 0: P = embed @ Wx^T + b ----------------
// 64 vocab rows per block (grid 500). Wx_w staged transposed in smem once.
__global__ __launch_bounds__(256) void prep_kernel(
    const float* __restrict__ embed, const float* __restrict__ Wx_w,
    const float* __restrict__ Wx_b)
{
    __shared__ float wsh[256];     // Wx_w transposed: wsh[j*16+i] = Wx_w[i*16+j]
    __shared__ float e[64][16];    // 64 embed rows

    int t = threadIdx.x;
    int v0 = blockIdx.x * 64;

    wsh[(t & 15) * 16 + (t >> 4)] = __ldg(Wx_w + t);
    {
        int vv = t >> 2, c = t & 3;
        ((float4*)e[vv])[c] = __ldg((const float4*)(embed + (size_t)(v0 + vv) * 16) + c);
    }
    __syncthreads();

    int i = t & 15;
    float w[16];
    #pragma unroll
    for (int j = 0; j < 16; j++) w[j] = wsh[j * 16 + i];
    float bias = __ldg(Wx_b + i);

    #pragma unroll
    for (int rep = 0; rep < 4; rep++) {
        int vl = (t >> 4) + rep * 16;
        const float4* er = (const float4*)e[vl];
        float4 e0 = er[0], e1 = er[1], e2 = er[2], e3 = er[3];
        float a0 = bias, a1 = 0.f, a2 = 0.f, a3 = 0.f;
        a0 = fmaf(w[0],  e0.x, a0);  a1 = fmaf(w[1],  e0.y, a1);
        a2 = fmaf(w[2],  e0.z, a2);  a3 = fmaf(w[3],  e0.w, a3);
        a0 = fmaf(w[4],  e1.x, a0);  a1 = fmaf(w[5],  e1.y, a1);
        a2 = fmaf(w[6],  e1.z, a2);  a3 = fmaf(w[7],  e1.w, a3);
        a0 = fmaf(w[8],  e2.x, a0);  a1 = fmaf(w[9],  e2.y, a1);
        a2 = fmaf(w[10], e2.z, a2);  a3 = fmaf(w[11], e2.w, a3);
        a0 = fmaf(w[12], e3.x, a0);  a1 = fmaf(w[13], e3.y, a1);
        a2 = fmaf(w[14], e3.z, a2);  a3 = fmaf(w[15], e3.w, a3);
        g_P[(size_t)(v0 + vl) * 16 + i] = (a0 + a1) + (a2 + a3);
    }
}

// ---------------- kernel 1: sequential recurrence, 4 lanes/row ----------------
// Thread (row, l): computes h[4l..4l+3] via f32x2 FFMA2 (weights for 4 Wh rows
// in 64 regs). Exchange: double-buffered smem (rows padded to 20 words —
// conflict-free), 1 STS.128 per thread-step + 1 __syncwarp; read back as
// 4 LDS.128. x: one aligned LDG.128 per thread-step from g_P.
// 16 rows/block (64 threads), grid 256 = 512 warps. Issue-bound by design.

__device__ __forceinline__ float tanh_fast(float z) {
    // 1 - 2/(e^{2z}+1): mul, ex2, add, rcp, fma
    float r;
    asm("{\n\t"
        ".reg .f32 t;\n\t"
        "mul.f32 t, %1, 0f4038AA3B;\n\t"
        "ex2.approx.f32 t, t;\n\t"
        "add.f32 t, t, 0f3F800000;\n\t"
        "rcp.approx.f32 t, t;\n\t"
        "fma.rn.f32 %0, t, 0fC0000000, 0f3F800000;\n\t"
        "}" : "=f"(r) : "f"(z));
    return r;
}

struct HRow { u64 p0, p1, p2, p3, p4, p5, p6, p7; };  // h[0..15] as 8 f32x2

__device__ __forceinline__ HRow load_hrow(const float* hr) {
    ulonglong2 a = *(const ulonglong2*)(hr + 0);    // h0..h3
    ulonglong2 b = *(const ulonglong2*)(hr + 4);    // h4..h7
    ulonglong2 c = *(const ulonglong2*)(hr + 8);    // h8..h11
    ulonglong2 d = *(const ulonglong2*)(hr + 12);   // h12..h15
    HRow h; h.p0 = a.x; h.p1 = a.y; h.p2 = b.x; h.p3 = b.y;
    h.p4 = c.x; h.p5 = c.y; h.p6 = d.x; h.p7 = d.y;
    return h;
}

__device__ __forceinline__ float dot16(const u64* wp, const HRow& h, float xo) {
    u64 a = pack2(xo, 0.0f), b = 0ull;
    a = ffma2(h.p0, wp[0], a);  b = ffma2(h.p1, wp[1], b);
    a = ffma2(h.p2, wp[2], a);  b = ffma2(h.p3, wp[3], b);
    a = ffma2(h.p4, wp[4], a);  b = ffma2(h.p5, wp[5], b);
    a = ffma2(h.p6, wp[6], a);  b = ffma2(h.p7, wp[7], b);
    float2 s = unpack2(add2(a, b));
    return tanh_fast(s.x + s.y);
}

#define HSTRIDE 20   // padded row stride (words): conflict-free for 8 rows/warp

__global__ __launch_bounds__(64) void rnn_kernel(
    const int* __restrict__ seq, const float* __restrict__ Wh)
{
    __shared__ float hbuf[2][16][HSTRIDE];

    int t = threadIdx.x;            // 0..63
    int r = t >> 2;                 // block-local row 0..15 (8 rows/warp)
    int l = t & 3;                  // lane within row
    int c0 = l * 4;                 // my output columns
    int g = blockIdx.x * 16 + r;    // global row (grid 256)

    // weights: Wh rows c0..c0+3, packed as f32x2 pairs (8 u64 per output row)
    u64 wp[4][8];
    #pragma unroll
    for (int o = 0; o < 4; o++) {
        const ulonglong2* wr = (const ulonglong2*)(Wh + (size_t)(c0 + o) * 16);
        ulonglong2 q0 = __ldg(wr), q1 = __ldg(wr + 1),
                   q2 = __ldg(wr + 2), q3 = __ldg(wr + 3);
        wp[o][0] = q0.x; wp[o][1] = q0.y; wp[o][2] = q1.x; wp[o][3] = q1.y;
        wp[o][4] = q2.x; wp[o][5] = q2.y; wp[o][6] = q3.x; wp[o][7] = q3.y;
    }

    const int* sr = seq + (size_t)g * T_DIM;
    const float* P = g_P;

    *(float4*)(&hbuf[0][r][c0]) = make_float4(0.f, 0.f, 0.f, 0.f);
    __syncthreads();

    // prologue: block0 x (4 steps, float4 each); tokens for blocks 1,2 in flight
    int4 tk  = __ldg((const int4*)sr);
    float4 x0 = __ldg((const float4*)(P + (size_t)tk.x * 16 + c0));
    float4 x1 = __ldg((const float4*)(P + (size_t)tk.y * 16 + c0));
    float4 x2 = __ldg((const float4*)(P + (size_t)tk.z * 16 + c0));
    float4 x3 = __ldg((const float4*)(P + (size_t)tk.w * 16 + c0));
    int4 nt1 = __ldg((const int4*)(sr + 4));
    int4 nt2 = __ldg((const int4*)(sr + 8));

    #define RSTEP(SRC, DST, X)                                               \
        {                                                                    \
            HRow hh = load_hrow(&hbuf[SRC][r][0]);                           \
            float n0 = dot16(wp[0], hh, (X).x);                              \
            float n1 = dot16(wp[1], hh, (X).y);                              \
            float n2 = dot16(wp[2], hh, (X).z);                              \
            float n3 = dot16(wp[3], hh, (X).w);                              \
            *(float4*)(&hbuf[DST][r][c0]) = make_float4(n0, n1, n2, n3);     \
            __syncwarp();                                                    \
        }

    for (int tt = 0; tt < T_DIM; tt += 4) {
        int tn = (tt + 12 < T_DIM) ? (tt + 12) : 0;     // clamped, tail unused
        int4 nn = __ldg((const int4*)(sr + tn));        // tokens block+3

        RSTEP(0, 1, x0)
        RSTEP(1, 0, x1)

        float4 p0 = __ldg((const float4*)(P + (size_t)nt1.x * 16 + c0));
        float4 p1 = __ldg((const float4*)(P + (size_t)nt1.y * 16 + c0));
        float4 p2 = __ldg((const float4*)(P + (size_t)nt1.z * 16 + c0));
        float4 p3 = __ldg((const float4*)(P + (size_t)nt1.w * 16 + c0));

        RSTEP(0, 1, x2)
        RSTEP(1, 0, x3)

        x0 = p0; x1 = p1; x2 = p2; x3 = p3;
        nt1 = nt2; nt2 = nn;
    }
    #undef RSTEP

    // T_DIM % 4 == 0 -> final state in buffer 0; write my 4 values
    float4 hf = *(const float4*)(&hbuf[0][r][c0]);
    *(float4*)(g_H + (size_t)g * 16 + c0) = hf;
}

// ---------------- kernel 2: out = H @ out_w^T + out_b via f32x2 ----------------
__global__ __launch_bounds__(256) void gemm_kernel(
    const float* __restrict__ out_w, const float* __restrict__ bias,
    float* __restrict__ out)
{
    __shared__ u64 hs[128 * 16];   // (h,h) packed, 16 KB

    int rb = blockIdx.y * 128;
    int vb = blockIdx.x * 1024;

    for (int idx = threadIdx.x; idx < 128 * 16; idx += 256) {
        float v = g_H[(size_t)rb * 16 + idx];
        hs[idx] = pack2(v, v);
    }
    __syncthreads();

    int v0 = vb + threadIdx.x * 4;
    if (v0 >= VOCAB) return;

    float wv[4][16];
    #pragma unroll
    for (int r = 0; r < 4; r++) {
        const float4* wr = (const float4*)(out_w + (size_t)(v0 + r) * 16);
        #pragma unroll
        for (int c = 0; c < 4; c++)
            ((float4*)wv[r])[c] = __ldg(wr + c);
    }
    u64 w2a[16], w2b[16];
    #pragma unroll
    for (int k = 0; k < 16; k++) {
        w2a[k] = pack2(wv[0][k], wv[1][k]);
        w2b[k] = pack2(wv[2][k], wv[3][k]);
    }
    u64 ba = *(const u64*)(bias + v0);
    u64 bb = *(const u64*)(bias + v0 + 2);

    for (int r = 0; r < 128; r++) {
        const ulonglong2* hp = (const ulonglong2*)(hs + r * 16);
        u64 aA = ba, aB = bb;
        #pragma unroll
        for (int k = 0; k < 16; k += 2) {
            ulonglong2 hh = hp[k >> 1];
            aA = ffma2(hh.x, w2a[k],     aA);
            aB = ffma2(hh.x, w2b[k],     aB);
            aA = ffma2(hh.y, w2a[k + 1], aA);
            aB = ffma2(hh.y, w2b[k + 1], aB);
        }
        float2 fa = unpack2(aA);
        float2 fb = unpack2(aB);
        __stcs((float4*)(out + (size_t)(rb + r) * VOCAB + v0),
               make_float4(fa.x, fa.y, fb.x, fb.y));
    }
}

// ---------------- launch ----------------
extern "C" void kernel_launch(void* const* d_in, const int* in_sizes, int n_in,
                              void* d_out, int out_size)
{
    const int*   seq   = (const int*)d_in[0];
    const float* embed = (const float*)d_in[1];
    const float* Wh    = (const float*)d_in[2];
    const float* Wx_w  = (const float*)d_in[3];
    const float* Wx_b  = (const float*)d_in[4];
    const float* out_w = (const float*)d_in[5];
    const float* out_b = (const float*)d_in[6];
    float* out = (float*)d_out;

    prep_kernel<<<VOCAB / 64, 256>>>(embed, Wx_w, Wx_b);          // 500 blocks

    rnn_kernel<<<B_DIM / 16, 64>>>(seq, Wh);                      // 256 blocks, 4 lanes/row

    dim3 ggrid((VOCAB + 1023) / 1024, B_DIM / 128);               // (32, 32)
    gemm_kernel<<<ggrid, 256>>>(out_w, out_b, out);
}

// round 11
// speedup vs baseline: 1.1030x; 1.1030x over previous
#include <cuda_runtime.h>
#include <cuda_bf16.h>
#include <cstdint>

typedef unsigned long long u64;

#define B_DIM 4096
#define T_DIM 1024
#define VOCAB 32000
#define HID 16

// ---------------- scratch (no allocations allowed) ----------------
__device__ float g_P[VOCAB * HID];   // projected embedding table: Wx@e + b (2 MB)
__device__ float g_H[B_DIM * HID];   // final hidden states (256 KB)

// ---------------- f32x2 helpers ----------------
__device__ __forceinline__ u64 pack2(float x, float y) {
    u64 r; asm("mov.b64 %0, {%1, %2};" : "=l"(r) : "f"(x), "f"(y)); return r;
}
__device__ __forceinline__ float2 unpack2(u64 v) {
    float2 f; asm("mov.b64 {%0, %1}, %2;" : "=f"(f.x), "=f"(f.y) : "l"(v)); return f;
}
__device__ __forceinline__ u64 ffma2(u64 a, u64 b, u64 c) {
    u64 d; asm("fma.rn.f32x2 %0, %1, %2, %3;" : "=l"(d) : "l"(a), "l"(b), "l"(c)); return d;
}
__device__ __forceinline__ u64 add2(u64 a, u64 b) {
    u64 d; asm("add.rn.f32x2 %0, %1, %2;" : "=l"(d) : "l"(a), "l"(b)); return d;
}

// ---------------- kernel 0: P = embed @ Wx^T + b ----------------
// 64 vocab rows per block (grid 500). Wx_w staged transposed in smem once.
__global__ __launch_bounds__(256) void prep_kernel(
    const float* __restrict__ embed, const float* __restrict__ Wx_w,
    const float* __restrict__ Wx_b)
{
    __shared__ float wsh[256];     // Wx_w transposed: wsh[j*16+i] = Wx_w[i*16+j]
    __shared__ float e[64][16];    // 64 embed rows

    int t = threadIdx.x;
    int v0 = blockIdx.x * 64;

    wsh[(t & 15) * 16 + (t >> 4)] = __ldg(Wx_w + t);
    {
        int vv = t >> 2, c = t & 3;
        ((float4*)e[vv])[c] = __ldg((const float4*)(embed + (size_t)(v0 + vv) * 16) + c);
    }
    __syncthreads();

    int i = t & 15;
    float w[16];
    #pragma unroll
    for (int j = 0; j < 16; j++) w[j] = wsh[j * 16 + i];
    float bias = __ldg(Wx_b + i);

    #pragma unroll
    for (int rep = 0; rep < 4; rep++) {
        int vl = (t >> 4) + rep * 16;
        const float4* er = (const float4*)e[vl];
        float4 e0 = er[0], e1 = er[1], e2 = er[2], e3 = er[3];
        float a0 = bias, a1 = 0.f, a2 = 0.f, a3 = 0.f;
        a0 = fmaf(w[0],  e0.x, a0);  a1 = fmaf(w[1],  e0.y, a1);
        a2 = fmaf(w[2],  e0.z, a2);  a3 = fmaf(w[3],  e0.w, a3);
        a0 = fmaf(w[4],  e1.x, a0);  a1 = fmaf(w[5],  e1.y, a1);
        a2 = fmaf(w[6],  e1.z, a2);  a3 = fmaf(w[7],  e1.w, a3);
        a0 = fmaf(w[8],  e2.x, a0);  a1 = fmaf(w[9],  e2.y, a1);
        a2 = fmaf(w[10], e2.z, a2);  a3 = fmaf(w[11], e2.w, a3);
        a0 = fmaf(w[12], e3.x, a0);  a1 = fmaf(w[13], e3.y, a1);
        a2 = fmaf(w[14], e3.z, a2);  a3 = fmaf(w[15], e3.w, a3);
        g_P[(size_t)(v0 + vl) * 16 + i] = (a0 + a1) + (a2 + a3);
    }
}

// ---------------- kernel 1: sequential recurrence ----------------
// R9 layout (16 lanes/row, 2 rows/warp, 16 rows/block, grid 256 = 2048 warps,
// ~3.46 warps/SMSP: issue-bound with latency hidden) + FFMA2 dot:
// each lane's dot16 = 8 fma.rn.f32x2 on packed pairs instead of 16 scalar FFMA.
// Exchange: double-buffered smem broadcast (1 STS.32 + __syncwarp per step,
// h read back as 4 LDS.128 = 8 u64 pairs). Tokens prefetched 3 blocks ahead.

__device__ __forceinline__ float tanh_fast(float z) {
    // accurate 1 - 2/(e^{2z}+1): mul, ex2, add, rcp, fma (MUFU.TANH too lossy
    // over 1024 steps: ~5e-4/step would random-walk past the 1e-3 gate)
    float r;
    asm("{\n\t"
        ".reg .f32 t;\n\t"
        "mul.f32 t, %1, 0f4038AA3B;\n\t"
        "ex2.approx.f32 t, t;\n\t"
        "add.f32 t, t, 0f3F800000;\n\t"
        "rcp.approx.f32 t, t;\n\t"
        "fma.rn.f32 %0, t, 0fC0000000, 0f3F800000;\n\t"
        "}" : "=f"(r) : "f"(z));
    return r;
}

__device__ __forceinline__ float stepdot2(const u64* __restrict__ wp,
                                          const float* __restrict__ hrow, float xp) {
    ulonglong2 q0 = *(const ulonglong2*)(hrow + 0);    // (h0,h1),(h2,h3)
    ulonglong2 q1 = *(const ulonglong2*)(hrow + 4);
    ulonglong2 q2 = *(const ulonglong2*)(hrow + 8);
    ulonglong2 q3 = *(const ulonglong2*)(hrow + 12);
    u64 a = pack2(xp, 0.0f), b = 0ull;
    a = ffma2(q0.x, wp[0], a);  b = ffma2(q0.y, wp[1], b);
    a = ffma2(q1.x, wp[2], a);  b = ffma2(q1.y, wp[3], b);
    a = ffma2(q2.x, wp[4], a);  b = ffma2(q2.y, wp[5], b);
    a = ffma2(q3.x, wp[6], a);  b = ffma2(q3.y, wp[7], b);
    float2 s = unpack2(add2(a, b));
    return tanh_fast(s.x + s.y);
}

__global__ __launch_bounds__(256) void rnn_kernel(
    const int* __restrict__ seq, const float* __restrict__ Wh)
{
    __shared__ float hbuf[2][16][16];

    int t = threadIdx.x;
    int lr = t >> 4;                   // block-local row 0..15 (2 rows per warp)
    int i  = t & 15;
    int g  = blockIdx.x * 16 + lr;     // grid = B_DIM/16 = 256
    unsigned rowmask = 0xFFFFu << ((t >> 4 & 1) * 16);

    // Wh row i packed as 8 f32x2 pairs
    u64 wp[8];
    {
        const ulonglong2* wr = (const ulonglong2*)(Wh + (size_t)i * 16);
        ulonglong2 a = __ldg(wr), b = __ldg(wr + 1),
                   c = __ldg(wr + 2), d = __ldg(wr + 3);
        wp[0] = a.x; wp[1] = a.y; wp[2] = b.x; wp[3] = b.y;
        wp[4] = c.x; wp[5] = c.y; wp[6] = d.x; wp[7] = d.y;
    }

    const int* sr = seq + (size_t)g * T_DIM;
    const float* P = g_P;
    const float* hb0 = hbuf[0][lr];
    const float* hb1 = hbuf[1][lr];

    hbuf[0][lr][i] = 0.0f;
    __syncwarp(rowmask);

    // prologue: block0 xp; tokens for blocks 1 and 2 in flight
    int4 tk  = __ldg((const int4*)sr);
    float x0 = __ldg(P + (size_t)tk.x * 16 + i);
    float x1 = __ldg(P + (size_t)tk.y * 16 + i);
    float x2 = __ldg(P + (size_t)tk.z * 16 + i);
    float x3 = __ldg(P + (size_t)tk.w * 16 + i);
    int4 nt1 = __ldg((const int4*)(sr + 4));
    int4 nt2 = __ldg((const int4*)(sr + 8));

    #define RSTEP(SRCP, DSTIDX, X)                                           \
        {                                                                    \
            float nv = stepdot2(wp, SRCP, X);                                \
            hbuf[DSTIDX][lr][i] = nv;                                        \
            __syncwarp(rowmask);                                             \
        }

    for (int tt = 0; tt < T_DIM; tt += 4) {
        int tn = (tt + 12 < T_DIM) ? (tt + 12) : 0;   // clamped, tail unused
        int4 nn = __ldg((const int4*)(sr + tn));      // tokens block+3

        RSTEP(hb0, 1, x0)
        RSTEP(hb1, 0, x1)

        float p0 = __ldg(P + (size_t)nt1.x * 16 + i); // next block's xp
        float p1 = __ldg(P + (size_t)nt1.y * 16 + i); // (tokens fetched 2 iters ago)
        float p2 = __ldg(P + (size_t)nt1.z * 16 + i);
        float p3 = __ldg(P + (size_t)nt1.w * 16 + i);

        RSTEP(hb0, 1, x2)
        RSTEP(hb1, 0, x3)

        x0 = p0; x1 = p1; x2 = p2; x3 = p3;
        nt1 = nt2; nt2 = nn;
    }
    #undef RSTEP

    // T_DIM % 4 == 0 -> final state in buffer 0
    g_H[(size_t)g * 16 + i] = hbuf[0][lr][i];
}

// ---------------- kernel 2: out = H @ out_w^T + out_b via f32x2 ----------------
// Streaming stores; sits at the DRAM write floor for the 524 MB output.
__global__ __launch_bounds__(256) void gemm_kernel(
    const float* __restrict__ out_w, const float* __restrict__ bias,
    float* __restrict__ out)
{
    __shared__ u64 hs[128 * 16];   // (h,h) packed, 16 KB

    int rb = blockIdx.y * 128;
    int vb = blockIdx.x * 1024;

    for (int idx = threadIdx.x; idx < 128 * 16; idx += 256) {
        float v = g_H[(size_t)rb * 16 + idx];
        hs[idx] = pack2(v, v);
    }
    __syncthreads();

    int v0 = vb + threadIdx.x * 4;
    if (v0 >= VOCAB) return;

    float wv[4][16];
    #pragma unroll
    for (int r = 0; r < 4; r++) {
        const float4* wr = (const float4*)(out_w + (size_t)(v0 + r) * 16);
        #pragma unroll
        for (int c = 0; c < 4; c++)
            ((float4*)wv[r])[c] = __ldg(wr + c);
    }
    u64 w2a[16], w2b[16];
    #pragma unroll
    for (int k = 0; k < 16; k++) {
        w2a[k] = pack2(wv[0][k], wv[1][k]);
        w2b[k] = pack2(wv[2][k], wv[3][k]);
    }
    u64 ba = *(const u64*)(bias + v0);
    u64 bb = *(const u64*)(bias + v0 + 2);

    for (int r = 0; r < 128; r++) {
        const ulonglong2* hp = (const ulonglong2*)(hs + r * 16);
        u64 aA = ba, aB = bb;
        #pragma unroll
        for (int k = 0; k < 16; k += 2) {
            ulonglong2 hh = hp[k >> 1];
            aA = ffma2(hh.x, w2a[k],     aA);
            aB = ffma2(hh.x, w2b[k],     aB);
            aA = ffma2(hh.y, w2a[k + 1], aA);
            aB = ffma2(hh.y, w2b[k + 1], aB);
        }
        float2 fa = unpack2(aA);
        float2 fb = unpack2(aB);
        __stcs((float4*)(out + (size_t)(rb + r) * VOCAB + v0),
               make_float4(fa.x, fa.y, fb.x, fb.y));
    }
}

// ---------------- launch ----------------
extern "C" void kernel_launch(void* const* d_in, const int* in_sizes, int n_in,
                              void* d_out, int out_size)
{
    const int*   seq   = (const int*)d_in[0];
    const float* embed = (const float*)d_in[1];
    const float* Wh    = (const float*)d_in[2];
    const float* Wx_w  = (const float*)d_in[3];
    const float* Wx_b  = (const float*)d_in[4];
    const float* out_w = (const float*)d_in[5];
    const float* out_b = (const float*)d_in[6];
    float* out = (float*)d_out;

    prep_kernel<<<VOCAB / 64, 256>>>(embed, Wx_w, Wx_b);          // 500 blocks

    rnn_kernel<<<B_DIM / 16, 256>>>(seq, Wh);                     // 256 blocks, 2048 warps

    dim3 ggrid((VOCAB + 1023) / 1024, B_DIM / 128);               // (32, 32)
    gemm_kernel<<<ggrid, 256>>>(out_w, out_b, out);
}